// round 2
// baseline (speedup 1.0000x reference)
#include <cuda_runtime.h>

#define MAX_E  131072
#define NTYPE  10
#define TILE_E 64

__device__ int g_count[NTYPE];
__device__ int g_off[NTYPE + 1];
__device__ int g_cursor[NTYPE];
__device__ int g_perm[MAX_E];

typedef unsigned long long u64;

__device__ __forceinline__ void ffma2(u64 &acc, u64 a, u64 b) {
    asm("fma.rn.f32x2 %0, %1, %2, %0;" : "+l"(acc) : "l"(a), "l"(b));
}

__device__ __forceinline__ float2 unpack2(u64 v) {
    float2 r;
    asm("mov.b64 {%0, %1}, %2;" : "=f"(r.x), "=f"(r.y) : "l"(v));
    return r;
}

// tanh via (e^{2x}-1)/(e^{2x}+1) with ex2/rcp approx; rel err ~1e-6
__device__ __forceinline__ float tanh_ex(float x) {
    x = fminf(fmaxf(x, -15.0f), 15.0f);
    float t;
    asm("ex2.approx.f32 %0, %1;" : "=f"(t) : "f"(x * 2.8853900817779268f));
    float r;
    asm("rcp.approx.f32 %0, %1;" : "=f"(r) : "f"(t + 1.0f));
    return (t - 1.0f) * r;
}

// ---------------- sort kernels ----------------

__global__ void k_zero() {
    if (threadIdx.x < NTYPE) g_count[threadIdx.x] = 0;
}

__global__ void k_hist(const int* __restrict__ bij, int n) {
    __shared__ int s[NTYPE];
    if (threadIdx.x < NTYPE) s[threadIdx.x] = 0;
    __syncthreads();
    for (int i = blockIdx.x * blockDim.x + threadIdx.x; i < n; i += gridDim.x * blockDim.x)
        atomicAdd(&s[bij[i]], 1);
    __syncthreads();
    if (threadIdx.x < NTYPE) atomicAdd(&g_count[threadIdx.x], s[threadIdx.x]);
}

__global__ void k_prefix() {
    if (threadIdx.x == 0) {
        int acc = 0;
        for (int t = 0; t < NTYPE; t++) {
            g_off[t] = acc;
            g_cursor[t] = acc;
            acc += g_count[t];
        }
        g_off[NTYPE] = acc;
    }
}

__global__ void k_scatter(const int* __restrict__ bij, int n) {
    __shared__ int s_cnt[NTYPE], s_base[NTYPE];
    int tid = threadIdx.x;
    if (tid < NTYPE) s_cnt[tid] = 0;
    __syncthreads();
    int i = blockIdx.x * blockDim.x + tid;
    int t = 0, lpos = 0;
    bool valid = (i < n);
    if (valid) {
        t = bij[i];
        lpos = atomicAdd(&s_cnt[t], 1);
    }
    __syncthreads();
    if (tid < NTYPE)
        s_base[tid] = s_cnt[tid] ? atomicAdd(&g_cursor[tid], s_cnt[tid]) : 0;
    __syncthreads();
    if (valid) g_perm[s_base[t] + lpos] = i;
}

// ---------------- main GEMM kernel ----------------
// Grid: (15, NTYPE). Block 256 = 32(tx: edge) x 8(ty: 8-output group).
// smem: sW[2][64][64] natural [o][k] (warp-uniform broadcast reads),
//       sD[32][64] float2 [kpair][edge] (conflict-free both directions).
// 48 KB static smem exactly. Bias in regs; perm read straight from global
// (one load per thread per tile; L1 resident).
// f32x2 accumulators hold even/odd-k partial sums; reduced at epilogue.

__global__ __launch_bounds__(256) void k_gemm(
    const float* __restrict__ desc,
    const float* __restrict__ layer1,
    const float* __restrict__ lin_w,
    const float* __restrict__ lin_b,
    float* __restrict__ out)
{
    __shared__ float  sW[2][64][64];
    __shared__ float2 sD[32][64];

    const int t   = blockIdx.y;
    const int tid = threadIdx.x;
    const int tx  = tid & 31;
    const int ty  = tid >> 5;
    const int ob  = ty * 8;

    // weights once per block
    {
        const float4* wt = (const float4*)(layer1 + t * 4096);
        const float4* lw = (const float4*)lin_w;
        float4* s0 = (float4*)&sW[0][0][0];
        float4* s1 = (float4*)&sW[1][0][0];
        #pragma unroll
        for (int i = tid; i < 1024; i += 256) {
            s0[i] = wt[i];
            s1[i] = lw[i];
        }
    }

    // bias for this thread's 8 outputs -> registers
    float bias[8];
    {
        float4 b0 = __ldg((const float4*)&lin_b[ob]);
        float4 b1 = __ldg((const float4*)&lin_b[ob + 4]);
        bias[0] = b0.x; bias[1] = b0.y; bias[2] = b0.z; bias[3] = b0.w;
        bias[4] = b1.x; bias[5] = b1.y; bias[6] = b1.z; bias[7] = b1.w;
    }

    const int seg_start = g_off[t];
    const int seg_end   = g_off[t + 1];

    const u64* dW = (const u64*)&sW[0][0][0];   // idx: o*32 + kp
    const u64* dL = (const u64*)&sW[1][0][0];
    const u64* dD = (const u64*)&sD[0][0];      // idx: kp*64 + e
    const int e0 = tx, e1 = tx + 32;
    const int eg = tid & 63;                    // gather lane (invariant, see below)

    for (int base = seg_start + blockIdx.x * TILE_E; base < seg_end;
         base += gridDim.x * TILE_E) {

        __syncthreads();  // previous tile fully consumed (sD reuse)

        // gather desc tile: pos = tid + 256*r, r=0..3; e = pos&63 == tid&63
        // so each thread gathers 4 float4s of ONE edge: i4 = (tid>>6) + 4*r
        int gidx = base + eg;
        int ge   = (gidx < seg_end) ? g_perm[gidx] : -1;
        #pragma unroll
        for (int r = 0; r < 4; r++) {
            int i4 = (tid >> 6) + 4 * r;
            float4 v = (ge >= 0) ? ((const float4*)desc)[ge * 16 + i4]
                                 : make_float4(0.f, 0.f, 0.f, 0.f);
            sD[2 * i4    ][eg] = make_float2(v.x, v.y);
            sD[2 * i4 + 1][eg] = make_float2(v.z, v.w);
        }
        __syncthreads();

        u64 aW0[8], aW1[8], aL0[8], aL1[8];
        #pragma unroll
        for (int j = 0; j < 8; j++) { aW0[j] = 0ull; aW1[j] = 0ull; aL0[j] = 0ull; aL1[j] = 0ull; }

        #pragma unroll 4
        for (int kp = 0; kp < 32; kp++) {
            u64 d0 = dD[kp * 64 + e0];
            u64 d1 = dD[kp * 64 + e1];
            #pragma unroll
            for (int j = 0; j < 8; j++) {
                u64 w = dW[(ob + j) * 32 + kp];
                ffma2(aW0[j], w, d0);
                ffma2(aW1[j], w, d1);
                u64 l = dL[(ob + j) * 32 + kp];
                ffma2(aL0[j], l, d0);
                ffma2(aL1[j], l, d1);
            }
        }

        // epilogue: reduce pair lanes, tanh, add adjust + bias, write
        {
            int i0 = base + e0;
            int p0 = (i0 < seg_end) ? g_perm[i0] : -1;
            if (p0 >= 0) {
                float res[8];
                #pragma unroll
                for (int j = 0; j < 8; j++) {
                    float2 w = unpack2(aW0[j]);
                    float2 l = unpack2(aL0[j]);
                    res[j] = tanh_ex(w.x + w.y) + (l.x + l.y) + bias[j];
                }
                float4* o4 = (float4*)&out[p0 * 64 + ob];
                o4[0] = make_float4(res[0], res[1], res[2], res[3]);
                o4[1] = make_float4(res[4], res[5], res[6], res[7]);
            }
            int i1 = base + e1;
            int p1 = (i1 < seg_end) ? g_perm[i1] : -1;
            if (p1 >= 0) {
                float res[8];
                #pragma unroll
                for (int j = 0; j < 8; j++) {
                    float2 w = unpack2(aW1[j]);
                    float2 l = unpack2(aL1[j]);
                    res[j] = tanh_ex(w.x + w.y) + (l.x + l.y) + bias[j];
                }
                float4* o4 = (float4*)&out[p1 * 64 + ob];
                o4[0] = make_float4(res[0], res[1], res[2], res[3]);
                o4[1] = make_float4(res[4], res[5], res[6], res[7]);
            }
        }
    }
}

// ---------------- launch ----------------

extern "C" void kernel_launch(void* const* d_in, const int* in_sizes, int n_in,
                              void* d_out, int out_size) {
    const int*   bij    = (const int*)d_in[0];
    const float* desc   = (const float*)d_in[1];
    const float* layer1 = (const float*)d_in[2];
    const float* lin_w  = (const float*)d_in[3];
    const float* lin_b  = (const float*)d_in[4];
    float*       out    = (float*)d_out;
    int n = in_sizes[0];
    if (n > MAX_E) n = MAX_E;

    k_zero<<<1, 32>>>();
    k_hist<<<148, 256>>>(bij, n);
    k_prefix<<<1, 32>>>();
    k_scatter<<<(n + 255) / 256, 256>>>(bij, n);
    k_gemm<<<dim3(15, NTYPE), 256>>>(desc, layer1, lin_w, lin_b, out);
}

// round 3
// speedup vs baseline: 2.0048x; 2.0048x over previous
#include <cuda_runtime.h>

#define MAX_E  131072
#define NTYPE  10
#define TILE_E 64
#define GRIDX  14

__device__ int g_count[NTYPE];
__device__ int g_off[NTYPE + 1];
__device__ int g_cursor[NTYPE];
__device__ int g_perm[MAX_E];

typedef unsigned long long u64;

__device__ __forceinline__ void ffma2(u64 &acc, u64 a, u64 b) {
    asm("fma.rn.f32x2 %0, %1, %2, %0;" : "+l"(acc) : "l"(a), "l"(b));
}

__device__ __forceinline__ float2 unpack2(u64 v) {
    float2 r;
    asm("mov.b64 {%0, %1}, %2;" : "=f"(r.x), "=f"(r.y) : "l"(v));
    return r;
}

// tanh via (e^{2x}-1)/(e^{2x}+1) with ex2/rcp approx; rel err ~1e-6
__device__ __forceinline__ float tanh_ex(float x) {
    x = fminf(fmaxf(x, -15.0f), 15.0f);
    float t;
    asm("ex2.approx.f32 %0, %1;" : "=f"(t) : "f"(x * 2.8853900817779268f));
    float r;
    asm("rcp.approx.f32 %0, %1;" : "=f"(r) : "f"(t + 1.0f));
    return (t - 1.0f) * r;
}

// ---------------- sort kernels ----------------

__global__ void k_zero() {
    if (threadIdx.x < NTYPE) g_count[threadIdx.x] = 0;
}

__global__ void k_hist(const int* __restrict__ bij, int n) {
    __shared__ int s[NTYPE];
    if (threadIdx.x < NTYPE) s[threadIdx.x] = 0;
    __syncthreads();
    for (int i = blockIdx.x * blockDim.x + threadIdx.x; i < n; i += gridDim.x * blockDim.x)
        atomicAdd(&s[bij[i]], 1);
    __syncthreads();
    if (threadIdx.x < NTYPE) atomicAdd(&g_count[threadIdx.x], s[threadIdx.x]);
}

__global__ void k_prefix() {
    if (threadIdx.x == 0) {
        int acc = 0;
        for (int t = 0; t < NTYPE; t++) {
            g_off[t] = acc;
            g_cursor[t] = acc;
            acc += g_count[t];
        }
        g_off[NTYPE] = acc;
    }
}

__global__ void k_scatter(const int* __restrict__ bij, int n) {
    __shared__ int s_cnt[NTYPE], s_base[NTYPE];
    int tid = threadIdx.x;
    if (tid < NTYPE) s_cnt[tid] = 0;
    __syncthreads();
    int i = blockIdx.x * blockDim.x + tid;
    int t = 0, lpos = 0;
    bool valid = (i < n);
    if (valid) {
        t = bij[i];
        lpos = atomicAdd(&s_cnt[t], 1);
    }
    __syncthreads();
    if (tid < NTYPE)
        s_base[tid] = s_cnt[tid] ? atomicAdd(&g_cursor[tid], s_cnt[tid]) : 0;
    __syncthreads();
    if (valid) g_perm[s_base[t] + lpos] = i;
}

// ---------------- main GEMM kernel ----------------
// Grid: (GRIDX, NTYPE) = 140 blocks = one wave on 148 SMs.
// Block 256 threads: og = tid&15 -> outputs 4og..4og+3, ty = tid>>4 -> edges 4ty..4ty+3.
// Thread tile 4 edges x 4 outputs x 2 mats = 32 u64 f32x2 accumulators.
// smem:
//   sWL[2][32][64] float2 : weight pairs, [mat][kpair][col], col = (o&3)*16 + (o>>2)
//                           -> 16-lane og-strided reads are conflict-free
//   sD [32][64]   float2 : desc pairs [kpair][edge], conflict-free both directions
// 48 KB static smem exactly. Next desc tile prefetched into registers during compute.

__global__ __launch_bounds__(256, 1) void k_gemm(
    const float* __restrict__ desc,
    const float* __restrict__ layer1,
    const float* __restrict__ lin_w,
    const float* __restrict__ lin_b,
    float* __restrict__ out)
{
    __shared__ float2 sWL[2][32][64];
    __shared__ float2 sD[32][64];

    const int t   = blockIdx.y;
    const int tid = threadIdx.x;
    const int og  = tid & 15;
    const int ty  = tid >> 4;

    // weights once per block, re-laid out to [kp][ (o&3)*16 + (o>>2) ]
    {
        const float4* wt = (const float4*)(layer1 + t * 4096);
        const float4* lw = (const float4*)lin_w;
        #pragma unroll
        for (int i = tid; i < 1024; i += 256) {
            int o   = i >> 4;
            int i4  = i & 15;
            int col = (o & 3) * 16 + (o >> 2);
            float4 v = wt[i];
            sWL[0][2 * i4    ][col] = make_float2(v.x, v.y);
            sWL[0][2 * i4 + 1][col] = make_float2(v.z, v.w);
            float4 u = lw[i];
            sWL[1][2 * i4    ][col] = make_float2(u.x, u.y);
            sWL[1][2 * i4 + 1][col] = make_float2(u.z, u.w);
        }
    }

    // bias for this thread's 4 outputs
    float4 bias = __ldg((const float4*)&lin_b[4 * og]);

    const int seg_start = g_off[t];
    const int seg_end   = g_off[t + 1];
    const int stride    = GRIDX * TILE_E;

    const u64* dW = (const u64*)&sWL[0][0][0];  // idx: kp*64 + col
    const u64* dL = (const u64*)&sWL[1][0][0];
    const u64* dD = (const u64*)&sD[0][0];      // idx: kp*64 + e
    const int eg  = tid & 63;                   // gather: this thread's edge
    const int i4b = tid >> 6;                   // gather: float4 index base

    // prefetch first tile
    int base = seg_start + blockIdx.x * TILE_E;
    int pge = -1;
    float4 pv[4];
    #pragma unroll
    for (int r = 0; r < 4; r++) pv[r] = make_float4(0.f, 0.f, 0.f, 0.f);
    if (base < seg_end) {
        int gidx = base + eg;
        pge = (gidx < seg_end) ? g_perm[gidx] : -1;
        if (pge >= 0) {
            #pragma unroll
            for (int r = 0; r < 4; r++)
                pv[r] = ((const float4*)desc)[pge * 16 + (i4b + 4 * r)];
        }
    }

    for (; base < seg_end; base += stride) {
        __syncthreads();   // sD from previous tile fully consumed
        #pragma unroll
        for (int r = 0; r < 4; r++) {
            int i4 = i4b + 4 * r;
            sD[2 * i4    ][eg] = make_float2(pv[r].x, pv[r].y);
            sD[2 * i4 + 1][eg] = make_float2(pv[r].z, pv[r].w);
        }
        __syncthreads();

        // prefetch next tile into registers (overlaps with compute below)
        {
            int nbase = base + stride;
            pge = -1;
            #pragma unroll
            for (int r = 0; r < 4; r++) pv[r] = make_float4(0.f, 0.f, 0.f, 0.f);
            if (nbase < seg_end) {
                int gidx = nbase + eg;
                pge = (gidx < seg_end) ? g_perm[gidx] : -1;
                if (pge >= 0) {
                    #pragma unroll
                    for (int r = 0; r < 4; r++)
                        pv[r] = ((const float4*)desc)[pge * 16 + (i4b + 4 * r)];
                }
            }
        }

        u64 aW[4][4], aL[4][4];
        #pragma unroll
        for (int j = 0; j < 4; j++)
            #pragma unroll
            for (int e = 0; e < 4; e++) { aW[j][e] = 0ull; aL[j][e] = 0ull; }

        #pragma unroll 8
        for (int kp = 0; kp < 32; kp++) {
            u64 d[4];
            #pragma unroll
            for (int e = 0; e < 4; e++) d[e] = dD[kp * 64 + 4 * ty + e];
            #pragma unroll
            for (int j = 0; j < 4; j++) {
                u64 w = dW[kp * 64 + 16 * j + og];
                u64 l = dL[kp * 64 + 16 * j + og];
                #pragma unroll
                for (int e = 0; e < 4; e++) {
                    ffma2(aW[j][e], w, d[e]);
                    ffma2(aL[j][e], l, d[e]);
                }
            }
        }

        // epilogue: this thread's 4 edges x 4 consecutive outputs
        #pragma unroll
        for (int e = 0; e < 4; e++) {
            int idx = base + 4 * ty + e;
            if (idx < seg_end) {
                int p = g_perm[idx];   // L1 hit (tile's perm loaded last iter)
                float res[4];
                #pragma unroll
                for (int j = 0; j < 4; j++) {
                    float2 w = unpack2(aW[j][e]);
                    float2 l = unpack2(aL[j][e]);
                    float b = (j == 0) ? bias.x : (j == 1) ? bias.y
                                       : (j == 2) ? bias.z : bias.w;
                    res[j] = tanh_ex(w.x + w.y) + (l.x + l.y) + b;
                }
                *(float4*)&out[p * 64 + 4 * og] =
                    make_float4(res[0], res[1], res[2], res[3]);
            }
        }
    }
}

// ---------------- launch ----------------

extern "C" void kernel_launch(void* const* d_in, const int* in_sizes, int n_in,
                              void* d_out, int out_size) {
    const int*   bij    = (const int*)d_in[0];
    const float* desc   = (const float*)d_in[1];
    const float* layer1 = (const float*)d_in[2];
    const float* lin_w  = (const float*)d_in[3];
    const float* lin_b  = (const float*)d_in[4];
    float*       out    = (float*)d_out;
    int n = in_sizes[0];
    if (n > MAX_E) n = MAX_E;

    k_zero<<<1, 32>>>();
    k_hist<<<128, 1024>>>(bij, n);
    k_prefix<<<1, 32>>>();
    k_scatter<<<(n + 1023) / 1024, 1024>>>(bij, n);
    k_gemm<<<dim3(GRIDX, NTYPE), 256>>>(desc, layer1, lin_w, lin_b, out);
}

// round 6
// speedup vs baseline: 3.6824x; 1.8367x over previous
#include <cuda_runtime.h>
#include <cstdint>

#define MAX_E    131072
#define NTYPE    10
#define NB_HIST  32
#define GRIDX    14
#define TILE_M   128

__device__ int g_part[NB_HIST][NTYPE];
__device__ int g_off[NTYPE + 1];
__device__ int g_cursor[NTYPE];
__device__ int g_perm[MAX_E];

typedef unsigned long long u64;
typedef unsigned int u32;

// ---------------- helpers ----------------

__device__ __forceinline__ u32 smem_u32(const void* p) {
    u32 a;
    asm("{ .reg .u64 t; cvta.to.shared.u64 t, %1; cvt.u32.u64 %0, t; }" : "=r"(a) : "l"(p));
    return a;
}

// cvt.rna.tf32.f32 takes a .b32 destination — output constraint must be "r"
__device__ __forceinline__ u32 to_tf32(float x) {
    u32 y;
    asm("cvt.rna.tf32.f32 %0, %1;" : "=r"(y) : "f"(x));
    return y;
}

__device__ __forceinline__ void mma8(float* d, u32 a0, u32 a1, u32 a2, u32 a3,
                                     u32 b0, u32 b1) {
    asm volatile(
        "mma.sync.aligned.m16n8k8.row.col.f32.tf32.tf32.f32 "
        "{%0,%1,%2,%3}, {%4,%5,%6,%7}, {%8,%9}, {%0,%1,%2,%3};"
        : "+f"(d[0]), "+f"(d[1]), "+f"(d[2]), "+f"(d[3])
        : "r"(a0), "r"(a1), "r"(a2), "r"(a3), "r"(b0), "r"(b1));
}

#define CP_ASYNC16(dst, src) \
    asm volatile("cp.async.cg.shared.global [%0], [%1], 16;" :: "r"(dst), "l"(src) : "memory")
#define CP_COMMIT() asm volatile("cp.async.commit_group;" ::: "memory")
#define CP_WAIT1()  asm volatile("cp.async.wait_group 1;" ::: "memory")
#define CP_WAIT0()  asm volatile("cp.async.wait_group 0;" ::: "memory")

// tanh via (e^{2x}-1)/(e^{2x}+1), ex2/rcp approx; rel err ~1e-6
__device__ __forceinline__ float tanh_ex(float x) {
    x = fminf(fmaxf(x, -15.0f), 15.0f);
    float t;
    asm("ex2.approx.f32 %0, %1;" : "=f"(t) : "f"(x * 2.8853900817779268f));
    float r;
    asm("rcp.approx.f32 %0, %1;" : "=f"(r) : "f"(t + 1.0f));
    return (t - 1.0f) * r;
}

// ---------------- sort kernels ----------------

__global__ void k_hist(const int* __restrict__ bij, int n) {
    __shared__ int s[NTYPE];
    int tid = threadIdx.x;
    if (tid < NTYPE) s[tid] = 0;
    __syncthreads();
    int lane = tid & 31;
    int stride = gridDim.x * blockDim.x;
    int base = blockIdx.x * blockDim.x + tid;
    int iters = (n + stride - 1) / stride;
    for (int it = 0; it < iters; it++) {
        int i = base + it * stride;
        bool valid = (i < n);
        unsigned act = __ballot_sync(0xffffffffu, valid);
        if (valid) {
            int t = bij[i];
            unsigned m = __match_any_sync(act, t);
            int leader = __ffs(m) - 1;
            if (lane == leader) atomicAdd(&s[t], __popc(m));
        }
    }
    __syncthreads();
    if (tid < NTYPE) g_part[blockIdx.x][tid] = s[tid];
}

__global__ void k_prefix() {
    __shared__ int c[NTYPE];
    int t = threadIdx.x;
    if (t < NTYPE) {
        int s = 0;
        #pragma unroll
        for (int b = 0; b < NB_HIST; b++) s += g_part[b][t];
        c[t] = s;
    }
    __syncthreads();
    if (t == 0) {
        int acc = 0;
        for (int i = 0; i < NTYPE; i++) {
            g_off[i] = acc;
            g_cursor[i] = acc;
            acc += c[i];
        }
        g_off[NTYPE] = acc;
    }
}

__global__ void k_scatter(const int* __restrict__ bij, int n) {
    __shared__ int s_cnt[NTYPE], s_base[NTYPE];
    int tid = threadIdx.x;
    int lane = tid & 31;
    if (tid < NTYPE) s_cnt[tid] = 0;
    __syncthreads();
    int i = blockIdx.x * blockDim.x + tid;
    bool valid = (i < n);
    unsigned act = __ballot_sync(0xffffffffu, valid);
    int t = 0, lpos = 0;
    if (valid) {
        t = bij[i];
        unsigned m = __match_any_sync(act, t);
        int leader = __ffs(m) - 1;
        unsigned lt;
        asm("mov.u32 %0, %%lanemask_lt;" : "=r"(lt));
        int rank = __popc(m & lt);
        int bse = 0;
        if (lane == leader) bse = atomicAdd(&s_cnt[t], __popc(m));
        bse = __shfl_sync(act, bse, leader);
        lpos = bse + rank;
    }
    __syncthreads();
    if (tid < NTYPE)
        s_base[tid] = s_cnt[tid] ? atomicAdd(&g_cursor[tid], s_cnt[tid]) : 0;
    __syncthreads();
    if (valid) g_perm[s_base[t] + lpos] = i;
}

// ---------------- tensor-core GEMM (mma.sync tf32) ----------------
// Grid (GRIDX, NTYPE) = 140 blocks, 256 threads = 8 warps.
// Per 128-edge tile: D[128x128] = A[128x64] x B[128x64]^T,
//   B rows 0-63 = W_t, 64-127 = lin_w.
// Warp w: mg = w>>1 -> edges [mg*32, mg*32+32); ng = w&1 -> W cols
//   [ng*32, +32) AND L cols [64+ng*32, +32) (8 n-blocks; W col o and
//   L col o+64 live in the SAME thread -> thread-local combine).
// B fragments (128 regs/thread) preloaded once per block. A tile in
// padded smem (row stride 68 floats -> bank 4e+k, conflict-free),
// double-buffered, filled by cp.async (wait_group 1 pipeline).
//
// smem floats: A0@0 (128x68), A1@8704, B@17408 (128x68), bias@26112.

#define ASTRIDE   68
#define F_A1      8704
#define F_B       17408
#define F_BIAS    26112
#define SMEM_BYTES ((F_BIAS + 64) * 4)

__global__ __launch_bounds__(256, 1)
void k_gemm(const float* __restrict__ desc,
            const float* __restrict__ layer1,
            const float* __restrict__ lin_w,
            const float* __restrict__ lin_b,
            float* __restrict__ out)
{
    extern __shared__ float sm[];
    float* B_s   = sm + F_B;
    float* sBias = sm + F_BIAS;

    const int t    = blockIdx.y;
    const int tid  = threadIdx.x;
    const int lane = tid & 31;
    const int warp = tid >> 5;
    const int g    = lane >> 2;   // groupID (row within fragment)
    const int tig  = lane & 3;    // thread-in-group (col within fragment)
    const int mg   = warp >> 1;   // edge group (32 edges)
    const int ng   = warp & 1;    // output group (32 W cols + 32 L cols)

    const int seg_start = g_off[t];
    const int seg_end   = g_off[t + 1];
    const int stride    = GRIDX * TILE_M;

    const u32 aBase[2] = { smem_u32(sm), smem_u32(sm + F_A1) };

    // fill B_s raw (cvt at fragment preload): 128 rows x 16 float4
    for (int i = tid; i < 128 * 16; i += 256) {
        int row = i >> 4;
        int c4  = i & 15;
        const float* src = (row < 64) ? (layer1 + t * 4096 + row * 64)
                                      : (lin_w + (row - 64) * 64);
        *(float4*)&B_s[row * ASTRIDE + c4 * 4] = ((const float4*)src)[c4];
    }
    if (tid < 64) sBias[tid] = lin_b[tid];

    // issue tile 0 gather: thread -> edge tid>>1, half tid&1 (8 x 16B)
    const int ge_e = tid >> 1;
    const int ge_h = tid & 1;
    int base0 = seg_start + blockIdx.x * TILE_M;
    if (base0 < seg_end) {
        int gidx = base0 + ge_e;
        if (gidx >= seg_end) gidx = seg_end - 1;
        int p = g_perm[gidx];
        const char* src = (const char*)(desc + p * 64 + ge_h * 32);
        u32 dst = aBase[0] + ge_e * (ASTRIDE * 4) + ge_h * 128;
        #pragma unroll
        for (int i = 0; i < 8; i++)
            CP_ASYNC16(dst + i * 16, src + i * 16);
    }
    CP_COMMIT();
    __syncthreads();

    // preload B fragments: bf[nb][kc][2], nb 0-3 = W blocks, 4-7 = L blocks
    u32 bf[8][8][2];
    #pragma unroll
    for (int nb = 0; nb < 8; nb++) {
        int cb  = (nb < 4) ? (ng * 4 + nb) : (8 + ng * 4 + (nb - 4));
        int row = cb * 8 + g;
        #pragma unroll
        for (int kc = 0; kc < 8; kc++) {
            bf[nb][kc][0] = to_tf32(B_s[row * ASTRIDE + kc * 8 + tig]);
            bf[nb][kc][1] = to_tf32(B_s[row * ASTRIDE + kc * 8 + tig + 4]);
        }
    }

    int buf = 0;
    for (int base = base0; base < seg_end; base += stride) {
        // issue next tile into other buffer
        int nbase = base + stride;
        if (nbase < seg_end) {
            int gidx = nbase + ge_e;
            if (gidx >= seg_end) gidx = seg_end - 1;
            int p = g_perm[gidx];
            const char* src = (const char*)(desc + p * 64 + ge_h * 32);
            u32 dst = aBase[buf ^ 1] + ge_e * (ASTRIDE * 4) + ge_h * 128;
            #pragma unroll
            for (int i = 0; i < 8; i++)
                CP_ASYNC16(dst + i * 16, src + i * 16);
        }
        CP_COMMIT();
        CP_WAIT1();        // current tile's group complete
        __syncthreads();

        const float* A = sm + (buf ? F_A1 : 0);

        #pragma unroll
        for (int mc = 0; mc < 2; mc++) {
            int eloc = mg * 32 + mc * 16 + g;   // local edge for c0/c1 rows
            float d[8][4];
            #pragma unroll
            for (int nb = 0; nb < 8; nb++)
                #pragma unroll
                for (int c = 0; c < 4; c++) d[nb][c] = 0.f;

            #pragma unroll
            for (int kc = 0; kc < 8; kc++) {
                u32 a0 = to_tf32(A[eloc * ASTRIDE + kc * 8 + tig]);
                u32 a1 = to_tf32(A[(eloc + 8) * ASTRIDE + kc * 8 + tig]);
                u32 a2 = to_tf32(A[eloc * ASTRIDE + kc * 8 + tig + 4]);
                u32 a3 = to_tf32(A[(eloc + 8) * ASTRIDE + kc * 8 + tig + 4]);
                #pragma unroll
                for (int nb = 0; nb < 8; nb++)
                    mma8(d[nb], a0, a1, a2, a3, bf[nb][kc][0], bf[nb][kc][1]);
            }

            // combine + store: rows eloc (c0/c1) and eloc+8 (c2/c3)
            int r0 = base + eloc;
            int r1 = r0 + 8;
            int p0 = (r0 < seg_end) ? g_perm[r0] : -1;
            int p1 = (r1 < seg_end) ? g_perm[r1] : -1;
            #pragma unroll
            for (int nb = 0; nb < 4; nb++) {
                int o = ng * 32 + nb * 8 + tig * 2;
                float b0 = sBias[o], b1 = sBias[o + 1];
                if (p0 >= 0) {
                    float2 v;
                    v.x = tanh_ex(d[nb][0]) + d[nb + 4][0] + b0;
                    v.y = tanh_ex(d[nb][1]) + d[nb + 4][1] + b1;
                    *(float2*)&out[p0 * 64 + o] = v;
                }
                if (p1 >= 0) {
                    float2 v;
                    v.x = tanh_ex(d[nb][2]) + d[nb + 4][2] + b0;
                    v.y = tanh_ex(d[nb][3]) + d[nb + 4][3] + b1;
                    *(float2*)&out[p1 * 64 + o] = v;
                }
            }
        }
        __syncthreads();   // A[buf] fully consumed before it is refilled
        buf ^= 1;
    }
    CP_WAIT0();            // drain any outstanding groups before exit
}

// ---------------- launch ----------------

extern "C" void kernel_launch(void* const* d_in, const int* in_sizes, int n_in,
                              void* d_out, int out_size) {
    const int*   bij    = (const int*)d_in[0];
    const float* desc   = (const float*)d_in[1];
    const float* layer1 = (const float*)d_in[2];
    const float* lin_w  = (const float*)d_in[3];
    const float* lin_b  = (const float*)d_in[4];
    float*       out    = (float*)d_out;
    int n = in_sizes[0];
    if (n > MAX_E) n = MAX_E;

    static int smem_set = 0;
    if (!smem_set) {
        cudaFuncSetAttribute(k_gemm, cudaFuncAttributeMaxDynamicSharedMemorySize,
                             SMEM_BYTES);
        smem_set = 1;
    }

    k_hist<<<NB_HIST, 1024>>>(bij, n);
    k_prefix<<<1, 32>>>();
    k_scatter<<<(n + 1023) / 1024, 1024>>>(bij, n);
    k_gemm<<<dim3(GRIDX, NTYPE), 256, SMEM_BYTES>>>(desc, layer1, lin_w, lin_b, out);
}

// round 7
// speedup vs baseline: 4.2051x; 1.1420x over previous
#include <cuda_runtime.h>
#include <cstdint>

#define MAX_E    131072
#define NTYPE    10
#define NB_HIST  32
#define GRIDX    29
#define TILE_M   64

__device__ int g_part[NB_HIST][NTYPE];
__device__ int g_off[NTYPE + 1];
__device__ int g_cursor[NTYPE];
__device__ int g_perm[MAX_E];

typedef unsigned long long u64;
typedef unsigned int u32;

// ---------------- helpers ----------------

__device__ __forceinline__ u32 smem_u32(const void* p) {
    u32 a;
    asm("{ .reg .u64 t; cvta.to.shared.u64 t, %1; cvt.u32.u64 %0, t; }" : "=r"(a) : "l"(p));
    return a;
}

__device__ __forceinline__ u32 to_tf32(float x) {
    u32 y;
    asm("cvt.rna.tf32.f32 %0, %1;" : "=r"(y) : "f"(x));
    return y;
}

__device__ __forceinline__ void mma8(float* d, u32 a0, u32 a1, u32 a2, u32 a3,
                                     u32 b0, u32 b1) {
    asm volatile(
        "mma.sync.aligned.m16n8k8.row.col.f32.tf32.tf32.f32 "
        "{%0,%1,%2,%3}, {%4,%5,%6,%7}, {%8,%9}, {%0,%1,%2,%3};"
        : "+f"(d[0]), "+f"(d[1]), "+f"(d[2]), "+f"(d[3])
        : "r"(a0), "r"(a1), "r"(a2), "r"(a3), "r"(b0), "r"(b1));
}

#define CP_ASYNC16(dst, src) \
    asm volatile("cp.async.cg.shared.global [%0], [%1], 16;" :: "r"(dst), "l"(src) : "memory")
#define CP_COMMIT() asm volatile("cp.async.commit_group;" ::: "memory")
#define CP_WAIT1()  asm volatile("cp.async.wait_group 1;" ::: "memory")
#define CP_WAIT0()  asm volatile("cp.async.wait_group 0;" ::: "memory")

// tanh via (e^{2x}-1)/(e^{2x}+1), ex2/rcp approx; rel err ~1e-6
__device__ __forceinline__ float tanh_ex(float x) {
    x = fminf(fmaxf(x, -15.0f), 15.0f);
    float t;
    asm("ex2.approx.f32 %0, %1;" : "=f"(t) : "f"(x * 2.8853900817779268f));
    float r;
    asm("rcp.approx.f32 %0, %1;" : "=f"(r) : "f"(t + 1.0f));
    return (t - 1.0f) * r;
}

// ---------------- sort kernels ----------------

__global__ void k_hist(const int* __restrict__ bij, int n) {
    __shared__ int s[NTYPE];
    int tid = threadIdx.x;
    if (tid < NTYPE) s[tid] = 0;
    __syncthreads();
    int lane = tid & 31;
    int stride = gridDim.x * blockDim.x;
    int base = blockIdx.x * blockDim.x + tid;
    int iters = (n + stride - 1) / stride;
    for (int it = 0; it < iters; it++) {
        int i = base + it * stride;
        bool valid = (i < n);
        unsigned act = __ballot_sync(0xffffffffu, valid);
        if (valid) {
            int t = bij[i];
            unsigned m = __match_any_sync(act, t);
            int leader = __ffs(m) - 1;
            if (lane == leader) atomicAdd(&s[t], __popc(m));
        }
    }
    __syncthreads();
    if (tid < NTYPE) g_part[blockIdx.x][tid] = s[tid];
}

__global__ void k_prefix() {
    __shared__ int c[NTYPE];
    int t = threadIdx.x;
    if (t < NTYPE) {
        int s = 0;
        #pragma unroll
        for (int b = 0; b < NB_HIST; b++) s += g_part[b][t];
        c[t] = s;
    }
    __syncthreads();
    if (t == 0) {
        int acc = 0;
        for (int i = 0; i < NTYPE; i++) {
            g_off[i] = acc;
            g_cursor[i] = acc;
            acc += c[i];
        }
        g_off[NTYPE] = acc;
    }
}

__global__ void k_scatter(const int* __restrict__ bij, int n) {
    __shared__ int s_cnt[NTYPE], s_base[NTYPE];
    int tid = threadIdx.x;
    int lane = tid & 31;
    if (tid < NTYPE) s_cnt[tid] = 0;
    __syncthreads();
    int i = blockIdx.x * blockDim.x + tid;
    bool valid = (i < n);
    unsigned act = __ballot_sync(0xffffffffu, valid);
    int t = 0, lpos = 0;
    if (valid) {
        t = bij[i];
        unsigned m = __match_any_sync(act, t);
        int leader = __ffs(m) - 1;
        unsigned lt;
        asm("mov.u32 %0, %%lanemask_lt;" : "=r"(lt));
        int rank = __popc(m & lt);
        int bse = 0;
        if (lane == leader) bse = atomicAdd(&s_cnt[t], __popc(m));
        bse = __shfl_sync(act, bse, leader);
        lpos = bse + rank;
    }
    __syncthreads();
    if (tid < NTYPE)
        s_base[tid] = s_cnt[tid] ? atomicAdd(&g_cursor[tid], s_cnt[tid]) : 0;
    __syncthreads();
    if (valid) g_perm[s_base[t] + lpos] = i;
}

// ---------------- tensor-core GEMM (mma.sync tf32, 2 CTAs/SM) ----------------
// Grid (GRIDX, NTYPE) = 290 blocks, 256 threads = 8 warps, 2 CTAs/SM.
// Per 64-edge tile: D[64x128] = A[64x64] x B[128x64]^T,
//   B rows 0-63 = W_t, 64-127 = lin_w.
// Warp w: mg = w>>2 -> edges [mg*32, +32); ng = w&3 -> W cols [ng*16, +16)
//   AND L cols [64+ng*16, +16) (4 n-blocks; W col o and L col o+64 in the
//   SAME thread -> thread-local combine). B frags = 64 regs/thread.
// A double-buffered in padded smem (stride 68 -> conflict-free), cp.async
// wait_group-1 pipeline; perm staged in smem alongside each buffer.
//
// smem floats: A0@0 (64x68), A1@4352, B@8704 (128x68), bias@17408,
//              perm@17472 (2 x 64 ints).

#define ASTRIDE   68
#define F_A1      4352
#define F_B       8704
#define F_BIAS    17408
#define F_PERM    17472
#define SMEM_BYTES ((F_PERM + 128) * 4)

__global__ __launch_bounds__(256, 2)
void k_gemm(const float* __restrict__ desc,
            const float* __restrict__ layer1,
            const float* __restrict__ lin_w,
            const float* __restrict__ lin_b,
            float* __restrict__ out)
{
    extern __shared__ float sm[];
    float* B_s    = sm + F_B;
    float* sBias  = sm + F_BIAS;
    int*   sPermB = (int*)(sm + F_PERM);

    const int t    = blockIdx.y;
    const int tid  = threadIdx.x;
    const int lane = tid & 31;
    const int warp = tid >> 5;
    const int g    = lane >> 2;   // fragment row group
    const int tig  = lane & 3;    // thread-in-group
    const int mg   = warp >> 2;   // edge group (32 edges)
    const int ng   = warp & 3;    // output group (16 W + 16 L cols)

    const int seg_start = g_off[t];
    const int seg_end   = g_off[t + 1];
    const int stride    = GRIDX * TILE_M;

    const u32 aBase[2] = { smem_u32(sm), smem_u32(sm + F_A1) };

    // fill B_s raw (cvt at fragment preload): 128 rows x 16 float4
    for (int i = tid; i < 128 * 16; i += 256) {
        int row = i >> 4;
        int c4  = i & 15;
        const float* src = (row < 64) ? (layer1 + t * 4096 + row * 64)
                                      : (lin_w + (row - 64) * 64);
        *(float4*)&B_s[row * ASTRIDE + c4 * 4] = ((const float4*)src)[c4];
    }
    if (tid < 64) sBias[tid] = lin_b[tid];

    // gather mapping: edge = tid>>2, quarter = tid&3 (4 x 16B per thread)
    const int ge_e = tid >> 2;
    const int ge_q = tid & 3;

    // issue tile 0 into buf0 (+ perm stage)
    int base0 = seg_start + blockIdx.x * TILE_M;
    if (base0 < seg_end) {
        int gidx = base0 + ge_e;
        bool v = (gidx < seg_end);
        int gc = v ? gidx : seg_end - 1;
        int p = g_perm[gc];
        if (ge_q == 0) sPermB[ge_e] = v ? p : -1;
        const char* src = (const char*)(desc + p * 64 + ge_q * 16);
        u32 dst = aBase[0] + ge_e * (ASTRIDE * 4) + ge_q * 64;
        CP_ASYNC16(dst, src);
        CP_ASYNC16(dst + 16, src + 16);
        CP_ASYNC16(dst + 32, src + 32);
        CP_ASYNC16(dst + 48, src + 48);
    }
    CP_COMMIT();
    __syncthreads();

    // preload B fragments: bf[nb][kc][2]; nb 0-1 = W blocks, 2-3 = L blocks
    u32 bf[4][8][2];
    #pragma unroll
    for (int nb = 0; nb < 4; nb++) {
        int cb  = (nb < 2) ? (ng * 2 + nb) : (8 + ng * 2 + (nb - 2));
        int row = cb * 8 + g;
        #pragma unroll
        for (int kc = 0; kc < 8; kc++) {
            bf[nb][kc][0] = to_tf32(B_s[row * ASTRIDE + kc * 8 + tig]);
            bf[nb][kc][1] = to_tf32(B_s[row * ASTRIDE + kc * 8 + tig + 4]);
        }
    }

    int buf = 0;
    for (int base = base0; base < seg_end; base += stride) {
        // issue next tile into the other buffer
        int nbase = base + stride;
        if (nbase < seg_end) {
            int gidx = nbase + ge_e;
            bool v = (gidx < seg_end);
            int gc = v ? gidx : seg_end - 1;
            int p = g_perm[gc];
            if (ge_q == 0) sPermB[(buf ^ 1) * 64 + ge_e] = v ? p : -1;
            const char* src = (const char*)(desc + p * 64 + ge_q * 16);
            u32 dst = aBase[buf ^ 1] + ge_e * (ASTRIDE * 4) + ge_q * 64;
            CP_ASYNC16(dst, src);
            CP_ASYNC16(dst + 16, src + 16);
            CP_ASYNC16(dst + 32, src + 32);
            CP_ASYNC16(dst + 48, src + 48);
        }
        CP_COMMIT();
        CP_WAIT1();        // current tile's group complete
        __syncthreads();

        const float* A    = sm + (buf ? F_A1 : 0);
        const int*   perm = sPermB + buf * 64;

        #pragma unroll
        for (int mc = 0; mc < 2; mc++) {
            int eloc = mg * 32 + mc * 16 + g;   // local edge (rows c0/c1)
            float d[4][4];
            #pragma unroll
            for (int nb = 0; nb < 4; nb++)
                #pragma unroll
                for (int c = 0; c < 4; c++) d[nb][c] = 0.f;

            #pragma unroll
            for (int kc = 0; kc < 8; kc++) {
                u32 a0 = to_tf32(A[eloc * ASTRIDE + kc * 8 + tig]);
                u32 a1 = to_tf32(A[(eloc + 8) * ASTRIDE + kc * 8 + tig]);
                u32 a2 = to_tf32(A[eloc * ASTRIDE + kc * 8 + tig + 4]);
                u32 a3 = to_tf32(A[(eloc + 8) * ASTRIDE + kc * 8 + tig + 4]);
                #pragma unroll
                for (int nb = 0; nb < 4; nb++)
                    mma8(d[nb], a0, a1, a2, a3, bf[nb][kc][0], bf[nb][kc][1]);
            }

            int p0 = perm[eloc];
            int p1 = perm[eloc + 8];
            #pragma unroll
            for (int nb = 0; nb < 2; nb++) {
                int o = ng * 16 + nb * 8 + tig * 2;
                float b0 = sBias[o], b1 = sBias[o + 1];
                if (p0 >= 0) {
                    float2 v;
                    v.x = tanh_ex(d[nb][0]) + d[nb + 2][0] + b0;
                    v.y = tanh_ex(d[nb][1]) + d[nb + 2][1] + b1;
                    *(float2*)&out[p0 * 64 + o] = v;
                }
                if (p1 >= 0) {
                    float2 v;
                    v.x = tanh_ex(d[nb][2]) + d[nb + 2][2] + b0;
                    v.y = tanh_ex(d[nb][3]) + d[nb + 2][3] + b1;
                    *(float2*)&out[p1 * 64 + o] = v;
                }
            }
        }
        __syncthreads();   // A[buf]/perm[buf] consumed before refill
        buf ^= 1;
    }
    CP_WAIT0();            // drain outstanding groups before exit
}

// ---------------- launch ----------------

extern "C" void kernel_launch(void* const* d_in, const int* in_sizes, int n_in,
                              void* d_out, int out_size) {
    const int*   bij    = (const int*)d_in[0];
    const float* desc   = (const float*)d_in[1];
    const float* layer1 = (const float*)d_in[2];
    const float* lin_w  = (const float*)d_in[3];
    const float* lin_b  = (const float*)d_in[4];
    float*       out    = (float*)d_out;
    int n = in_sizes[0];
    if (n > MAX_E) n = MAX_E;

    static int smem_set = 0;
    if (!smem_set) {
        cudaFuncSetAttribute(k_gemm, cudaFuncAttributeMaxDynamicSharedMemorySize,
                             SMEM_BYTES);
        smem_set = 1;
    }

    k_hist<<<NB_HIST, 1024>>>(bij, n);
    k_prefix<<<1, 32>>>();
    k_scatter<<<(n + 1023) / 1024, 1024>>>(bij, n);
    k_gemm<<<dim3(GRIDX, NTYPE), 256, SMEM_BYTES>>>(desc, layer1, lin_w, lin_b, out);
}